// round 5
// baseline (speedup 1.0000x reference)
#include <cuda_runtime.h>

#define THREADS 512
#define NW (THREADS / 32)        // 16 warps
#define B_ROWS 2048
#define RPT (B_ROWS / THREADS)   // 4 rows per thread
#define BN_EPS 1e-5f

typedef unsigned long long ull;
typedef long long ll;

__device__ __forceinline__ ull pack2(float lo, float hi) {
    ull r; asm("mov.b64 %0, {%1, %2};" : "=l"(r) : "f"(lo), "f"(hi)); return r;
}
__device__ __forceinline__ void unpack2(ull v, float& lo, float& hi) {
    asm("mov.b64 {%0, %1}, %2;" : "=f"(lo), "=f"(hi) : "l"(v));
}
__device__ __forceinline__ ull fma2(ull a, ull b, ull c) {
    ull d; asm("fma.rn.f32x2 %0, %1, %2, %3;" : "=l"(d) : "l"(a), "l"(b), "l"(c)); return d;
}
// accurate tanh (~1e-7 rel): MUFU.TANH at ~5e-4 is too close to the 1e-3 gate
__device__ __forceinline__ float ftanh(float x) {
    float e = __expf(2.0f * x);
    return 1.0f - __fdividef(2.0f, e + 1.0f);
}

// XOR-swizzled float4-column index for a [rows][16]-float smem tile: conflict-free
// (minimum-phase) for both 4-lane-per-row staging STS.128 and row-per-lane LDS.128.
__device__ __forceinline__ int swz(int row, int part) {
    return row * 16 + (((part + (row >> 1)) & 3) << 2);
}

// One block = G consecutive terms over the full batch. The 2048x8G activations
// live packed-in-place in the f32x2 accumulators (tanh overwrites acc) so the
// per-thread register peak stays under the 128-reg cap -> no local-memory spills.
// All global traffic is >=64B-contiguous (DRAM granularity).
template<int G>
__global__ void __launch_bounds__(THREADS, 1)
term_layer_kernel(const float* __restrict__ xin, ll xstride, int colmult,
                  const float* __restrict__ Wp,  const float* __restrict__ bp,
                  const float* __restrict__ gp,  const float* __restrict__ bep,
                  const float* __restrict__ Wap, const float* __restrict__ bap,
                  const float* __restrict__ gap, const float* __restrict__ beap,
                  float* __restrict__ out_t, float* __restrict__ out_a, int M)
{
    constexpr int F  = 8 * G;    // features per block
    constexpr int FA = 2 * G;    // aux features per block
    constexpr int DC = 16;       // staged input dims per chunk (64B per row)
    constexpr int NCH = 64 / DC;
    constexpr int P4  = DC / 4;

    extern __shared__ float sm[];
    float* sh_x   = sm;                      // [2048*16] swizzled; reused as store tile
    float* sh_w   = sm + B_ROWS * DC;        // [G*512]
    float* red    = sh_w + G * 512;          // [F*NW*2]
    float* stA    = red + F * NW * 2;        // [F]
    float* stB    = stA + F;
    float* saA    = stB + F;                 // [FA]
    float* saB    = saA + FA;
    float* sb0    = saB + FA;                // [F]
    float* sg0    = sb0 + F;
    float* sbe0   = sg0 + F;
    float* swa    = sbe0 + F;                // [G*16]
    float* sba    = swa + G * 16;            // [FA]
    float* sga    = sba + FA;
    float* sbea   = sga + FA;

    const int tid  = threadIdx.x;
    const int lane = tid & 31;
    const int warp = tid >> 5;
    const int m0   = blockIdx.x * G;
    const ll  colbase = (ll)m0 * colmult;

    // ---- params to smem ----
    for (int i = tid; i < G * 512; i += THREADS) sh_w[i] = Wp[(ll)m0 * 512 + i];
    if (tid < F) {
        sb0[tid]  = bp[m0 * 8 + tid];
        sg0[tid]  = gp[m0 * 8 + tid];
        sbe0[tid] = bep[m0 * 8 + tid];
    }
    if (tid < G * 16) swa[tid] = Wap[m0 * 16 + tid];
    if (tid < FA) {
        sba[tid]  = bap[m0 * 2 + tid];
        sga[tid]  = gap[m0 * 2 + tid];
        sbea[tid] = beap[m0 * 2 + tid];
    }

    // ---- Phase 1: GEMM (64 -> F), x staged in coalesced 64B-per-row chunks ----
    ull acc[RPT][4 * G];
    #pragma unroll
    for (int r = 0; r < RPT; ++r)
        #pragma unroll
        for (int j = 0; j < 4 * G; ++j) acc[r][j] = 0ull;

    const ulonglong2* shw2 = reinterpret_cast<const ulonglong2*>(sh_w);

    #pragma unroll 1
    for (int c = 0; c < NCH; ++c) {
        __syncthreads();                       // prev chunk consumed (also orders params)
        #pragma unroll
        for (int jj = 0; jj < (B_ROWS * P4) / THREADS; ++jj) {
            int j    = tid + jj * THREADS;
            int row  = j >> 2;
            int part = j & 3;
            const float4 v = *reinterpret_cast<const float4*>(
                xin + (ll)row * xstride + colbase + c * DC + part * 4);
            *reinterpret_cast<float4*>(&sh_x[swz(row, part)]) = v;
        }
        __syncthreads();

        #pragma unroll
        for (int p4 = 0; p4 < P4; ++p4) {
            float xv[RPT][4];
            #pragma unroll
            for (int r = 0; r < RPT; ++r) {
                const float4 v = *reinterpret_cast<const float4*>(
                    &sh_x[swz(tid + r * THREADS, p4)]);
                xv[r][0] = v.x; xv[r][1] = v.y; xv[r][2] = v.z; xv[r][3] = v.w;
            }
            #pragma unroll
            for (int dd = 0; dd < 4; ++dd) {
                int k = c * DC + p4 * 4 + dd;
                ull w[4 * G];
                #pragma unroll
                for (int g = 0; g < G; ++g) {
                    ulonglong2 w01 = shw2[(g * 64 + k) * 2];
                    ulonglong2 w23 = shw2[(g * 64 + k) * 2 + 1];
                    w[g * 4 + 0] = w01.x; w[g * 4 + 1] = w01.y;
                    w[g * 4 + 2] = w23.x; w[g * 4 + 3] = w23.y;
                }
                #pragma unroll
                for (int r = 0; r < RPT; ++r) {
                    ull xx = pack2(xv[r][dd], xv[r][dd]);
                    #pragma unroll
                    for (int j = 0; j < 4 * G; ++j) acc[r][j] = fma2(xx, w[j], acc[r][j]);
                }
            }
        }
    }

    // ---- Phase 2: bias + tanh IN PLACE (acc becomes packed tanh values) ----
    #pragma unroll
    for (int r = 0; r < RPT; ++r)
        #pragma unroll
        for (int j = 0; j < 4 * G; ++j) {
            int P = (j >> 2) * 8 + (j & 3) * 2;
            float lo, hi; unpack2(acc[r][j], lo, hi);
            acc[r][j] = pack2(ftanh(lo + sb0[P]), ftanh(hi + sb0[P + 1]));
        }

    // ---- batch stats per feature ----
    #pragma unroll
    for (int j = 0; j < 4 * G; ++j) {
        float s0 = 0.f, q0 = 0.f, s1 = 0.f, q1 = 0.f;
        #pragma unroll
        for (int r = 0; r < RPT; ++r) {
            float lo, hi; unpack2(acc[r][j], lo, hi);
            s0 += lo; q0 += lo * lo;
            s1 += hi; q1 += hi * hi;
        }
        #pragma unroll
        for (int o = 16; o; o >>= 1) {
            s0 += __shfl_xor_sync(0xffffffffu, s0, o);
            q0 += __shfl_xor_sync(0xffffffffu, q0, o);
            s1 += __shfl_xor_sync(0xffffffffu, s1, o);
            q1 += __shfl_xor_sync(0xffffffffu, q1, o);
        }
        if (lane == 0) {
            int P = (j >> 2) * 8 + (j & 3) * 2;
            red[P * NW + warp]           = s0;
            red[(F + P) * NW + warp]     = q0;
            red[(P + 1) * NW + warp]     = s1;
            red[(F + P + 1) * NW + warp] = q1;
        }
    }
    __syncthreads();
    if (tid < F) {
        int f = tid;
        float s = 0.f, ss = 0.f;
        #pragma unroll
        for (int w = 0; w < NW; ++w) { s += red[f * NW + w]; ss += red[(F + f) * NW + w]; }
        float mu  = s  * (1.f / B_ROWS);
        float var = ss * (1.f / B_ROWS) - mu * mu;
        float a   = sg0[f] * rsqrtf(var + BN_EPS);
        stA[f] = a;
        stB[f] = sbe0[f] - mu * a;
    }
    __syncthreads();

    // ---- Phase 3: normalize -> swizzled tile -> coalesced STG; aux in same pass ----
    float* tile = sh_x;                         // reuse (GEMM done)
    float av[RPT][FA];
    #pragma unroll 1
    for (int q = 0; q < RPT; ++q) {
        float tn[F];
        #pragma unroll
        for (int j = 0; j < 4 * G; ++j) {
            int P = (j >> 2) * 8 + (j & 3) * 2;
            float lo, hi; unpack2(acc[q][j], lo, hi);
            tn[P]     = fmaf(stA[P],     lo, stB[P]);
            tn[P + 1] = fmaf(stA[P + 1], hi, stB[P + 1]);
        }

        #pragma unroll
        for (int part = 0; part < F / 4; ++part) {
            float4 v = make_float4(tn[part * 4], tn[part * 4 + 1],
                                   tn[part * 4 + 2], tn[part * 4 + 3]);
            *reinterpret_cast<float4*>(&tile[swz(tid, part)]) = v;
        }
        #pragma unroll
        for (int g = 0; g < G; ++g)
            #pragma unroll
            for (int k = 0; k < 2; ++k) {
                float a = sba[g * 2 + k];
                #pragma unroll
                for (int h = 0; h < 8; ++h)
                    a = fmaf(tn[g * 8 + h], swa[(g * 8 + h) * 2 + k], a);
                av[q][g * 2 + k] = ftanh(a);
            }
        __syncthreads();

        constexpr int PT = F / 4;               // float4 parts per output row
        #pragma unroll
        for (int jj = 0; jj < (512 * PT) / THREADS; ++jj) {
            int j    = tid + jj * THREADS;
            int row  = j / PT;
            int part = j % PT;
            int grow = q * THREADS + row;
            *reinterpret_cast<float4*>(&out_t[(ll)grow * M * 8 + m0 * 8 + part * 4]) =
                *reinterpret_cast<const float4*>(&tile[swz(row, part)]);
        }
        __syncthreads();
    }

    // ---- Phase 4: aux stats + store ----
    #pragma unroll
    for (int f = 0; f < FA; ++f) {
        float s = 0.f, ss = 0.f;
        #pragma unroll
        for (int r = 0; r < RPT; ++r) { float v = av[r][f]; s += v; ss += v * v; }
        #pragma unroll
        for (int o = 16; o; o >>= 1) {
            s  += __shfl_xor_sync(0xffffffffu, s, o);
            ss += __shfl_xor_sync(0xffffffffu, ss, o);
        }
        if (lane == 0) { red[f * NW + warp] = s; red[(FA + f) * NW + warp] = ss; }
    }
    __syncthreads();
    if (tid < FA) {
        int f = tid;
        float s = 0.f, ss = 0.f;
        #pragma unroll
        for (int w = 0; w < NW; ++w) { s += red[f * NW + w]; ss += red[(FA + f) * NW + w]; }
        float mu  = s  * (1.f / B_ROWS);
        float var = ss * (1.f / B_ROWS) - mu * mu;
        float a   = sga[f] * rsqrtf(var + BN_EPS);
        saA[f] = a;
        saB[f] = sbea[f] - mu * a;
    }
    __syncthreads();

    #pragma unroll
    for (int r = 0; r < RPT; ++r) {
        int b = tid + r * THREADS;
        ll obase = ((ll)b * M + m0) * 2;
        if (G == 2) {
            float4 v;
            v.x = fmaf(saA[0], av[r][0], saB[0]);
            v.y = fmaf(saA[1], av[r][1], saB[1]);
            v.z = fmaf(saA[2], av[r][2], saB[2]);
            v.w = fmaf(saA[3], av[r][3], saB[3]);
            *reinterpret_cast<float4*>(&out_a[obase]) = v;
        } else {
            float2 v;
            v.x = fmaf(saA[0], av[r][0], saB[0]);
            v.y = fmaf(saA[1], av[r][1], saB[1]);
            *reinterpret_cast<float2*>(&out_a[obase]) = v;
        }
    }
}

// Output layout: (aux0, aux1, t0, t1) flattened, fp32
static const ll OFF_A0 = 0;
static const ll OFF_A1 = 2048LL * 8192 * 2;            // 33,554,432
static const ll OFF_T0 = OFF_A1 + 2048LL * 1024 * 2;   // 37,748,736
static const ll OFF_T1 = OFF_T0 + 2048LL * 8192 * 8;   // 171,966,464

template<int G>
static inline int smem_bytes() {
    int F = 8 * G, FA = 2 * G;
    return (B_ROWS * 16 + G * 512 + F * NW * 2 + 2 * F + 2 * FA
            + 3 * F + G * 16 + 3 * FA) * 4;
}

extern "C" void kernel_launch(void* const* d_in, const int* in_sizes, int n_in,
                              void* d_out, int out_size)
{
    const float* x    = (const float*)d_in[0];
    const float* W0   = (const float*)d_in[1];
    const float* b0   = (const float*)d_in[2];
    const float* g0   = (const float*)d_in[3];
    const float* be0  = (const float*)d_in[4];
    const float* Wa0  = (const float*)d_in[5];
    const float* ba0  = (const float*)d_in[6];
    const float* ga0  = (const float*)d_in[7];
    const float* bea0 = (const float*)d_in[8];
    const float* W1   = (const float*)d_in[9];
    const float* b1   = (const float*)d_in[10];
    const float* g1   = (const float*)d_in[11];
    const float* be1  = (const float*)d_in[12];
    const float* Wa1  = (const float*)d_in[13];
    const float* ba1  = (const float*)d_in[14];
    const float* ga1  = (const float*)d_in[15];
    const float* bea1 = (const float*)d_in[16];

    float* out  = (float*)d_out;
    float* aux0 = out + OFF_A0;
    float* aux1 = out + OFF_A1;
    float* t0   = out + OFF_T0;
    float* t1   = out + OFF_T1;

    const int s0 = smem_bytes<2>();   // ~138 KB
    const int s1 = smem_bytes<1>();   // ~135 KB
    cudaFuncSetAttribute(reinterpret_cast<const void*>(term_layer_kernel<2>),
                         cudaFuncAttributeMaxDynamicSharedMemorySize, s0);
    cudaFuncSetAttribute(reinterpret_cast<const void*>(term_layer_kernel<1>),
                         cudaFuncAttributeMaxDynamicSharedMemorySize, s1);

    // Layer 0: 8192 terms, 2 per block; all blocks stream the same x [2048,64]
    term_layer_kernel<2><<<8192 / 2, THREADS, s0>>>(
        x, 64, 0, W0, b0, g0, be0, Wa0, ba0, ga0, bea0, t0, aux0, 8192);

    // Layer 1: 1024 roots, 1 per block; each reads its 64-col slice of t0 [2048, 65536]
    term_layer_kernel<1><<<1024, THREADS, s1>>>(
        t0, 65536, 64, W1, b1, g1, be1, Wa1, ba1, ga1, bea1, t1, aux1, 1024);
}

// round 6
// speedup vs baseline: 1.2125x; 1.2125x over previous
#include <cuda_runtime.h>

#define THREADS 512
#define NW (THREADS / 32)        // 16 warps
#define B_ROWS 2048
#define RPT (B_ROWS / THREADS)   // 4 rows per thread
#define BN_EPS 1e-5f

typedef unsigned long long ull;
typedef long long ll;

__device__ __forceinline__ ull pack2(float lo, float hi) {
    ull r; asm("mov.b64 %0, {%1, %2};" : "=l"(r) : "f"(lo), "f"(hi)); return r;
}
__device__ __forceinline__ void unpack2(ull v, float& lo, float& hi) {
    asm("mov.b64 {%0, %1}, %2;" : "=f"(lo), "=f"(hi) : "l"(v));
}
__device__ __forceinline__ ull fma2(ull a, ull b, ull c) {
    ull d; asm("fma.rn.f32x2 %0, %1, %2, %3;" : "=l"(d) : "l"(a), "l"(b), "l"(c)); return d;
}
// accurate tanh (~1e-7 rel): MUFU.TANH at ~5e-4 is too close to the 1e-3 gate
__device__ __forceinline__ float ftanh(float x) {
    float e = __expf(2.0f * x);
    return 1.0f - __fdividef(2.0f, e + 1.0f);
}

// XOR-swizzled float4-column index for a [rows][16]-float smem tile.
__device__ __forceinline__ int swz(int row, int part) {
    return row * 16 + (((part + (row >> 1)) & 3) << 2);
}

// ============================ L0 kernel (R4 structure) ============================
// Block = 2 consecutive terms over the full batch; x staged via coalesced 64B-per-row
// chunks into swizzled smem; t stores transposed through a swizzled smem tile.
// mofs allows splitting the grid into several launches (profiling visibility).
__global__ void __launch_bounds__(THREADS, 1)
l0_kernel(const float* __restrict__ xin, int mofs,
          const float* __restrict__ Wp,  const float* __restrict__ bp,
          const float* __restrict__ gp,  const float* __restrict__ bep,
          const float* __restrict__ Wap, const float* __restrict__ bap,
          const float* __restrict__ gap, const float* __restrict__ beap,
          float* __restrict__ out_t, float* __restrict__ out_a, int M)
{
    constexpr int G  = 2;
    constexpr int F  = 16;
    constexpr int FA = 4;
    constexpr int DC = 16;
    constexpr int NCH = 64 / DC;
    constexpr int P4  = DC / 4;

    extern __shared__ float sm[];
    float* sh_x   = sm;                      // [2048*16] swizzled; reused as store tile
    float* sh_w   = sm + B_ROWS * DC;        // [G*512]
    float* red    = sh_w + G * 512;          // [F*NW*2]
    float* stA    = red + F * NW * 2;        // [F]
    float* stB    = stA + F;
    float* saA    = stB + F;                 // [FA]
    float* saB    = saA + FA;
    float* sb0    = saB + FA;                // [F]
    float* sg0    = sb0 + F;
    float* sbe0   = sg0 + F;
    float* swa    = sbe0 + F;                // [G*16]
    float* sba    = swa + G * 16;            // [FA]
    float* sga    = sba + FA;
    float* sbea   = sga + FA;

    const int tid  = threadIdx.x;
    const int lane = tid & 31;
    const int warp = tid >> 5;
    const int m0   = (blockIdx.x + mofs) * G;

    // ---- params to smem ----
    for (int i = tid; i < G * 512; i += THREADS) sh_w[i] = Wp[(ll)m0 * 512 + i];
    if (tid < F) {
        sb0[tid]  = bp[m0 * 8 + tid];
        sg0[tid]  = gp[m0 * 8 + tid];
        sbe0[tid] = bep[m0 * 8 + tid];
    }
    if (tid < G * 16) swa[tid] = Wap[m0 * 16 + tid];
    if (tid < FA) {
        sba[tid]  = bap[m0 * 2 + tid];
        sga[tid]  = gap[m0 * 2 + tid];
        sbea[tid] = beap[m0 * 2 + tid];
    }

    // ---- Phase 1: GEMM (64 -> 16) ----
    ull acc[RPT][4 * G];
    #pragma unroll
    for (int r = 0; r < RPT; ++r)
        #pragma unroll
        for (int j = 0; j < 4 * G; ++j) acc[r][j] = 0ull;

    const ulonglong2* shw2 = reinterpret_cast<const ulonglong2*>(sh_w);

    #pragma unroll 1
    for (int c = 0; c < NCH; ++c) {
        __syncthreads();
        #pragma unroll
        for (int jj = 0; jj < (B_ROWS * P4) / THREADS; ++jj) {
            int j    = tid + jj * THREADS;
            int row  = j >> 2;
            int part = j & 3;
            const float4 v = *reinterpret_cast<const float4*>(
                xin + (ll)row * 64 + c * DC + part * 4);
            *reinterpret_cast<float4*>(&sh_x[swz(row, part)]) = v;
        }
        __syncthreads();

        #pragma unroll
        for (int p4 = 0; p4 < P4; ++p4) {
            float xv[RPT][4];
            #pragma unroll
            for (int r = 0; r < RPT; ++r) {
                const float4 v = *reinterpret_cast<const float4*>(
                    &sh_x[swz(tid + r * THREADS, p4)]);
                xv[r][0] = v.x; xv[r][1] = v.y; xv[r][2] = v.z; xv[r][3] = v.w;
            }
            #pragma unroll
            for (int dd = 0; dd < 4; ++dd) {
                int k = c * DC + p4 * 4 + dd;
                ull w[4 * G];
                #pragma unroll
                for (int g = 0; g < G; ++g) {
                    ulonglong2 w01 = shw2[(g * 64 + k) * 2];
                    ulonglong2 w23 = shw2[(g * 64 + k) * 2 + 1];
                    w[g * 4 + 0] = w01.x; w[g * 4 + 1] = w01.y;
                    w[g * 4 + 2] = w23.x; w[g * 4 + 3] = w23.y;
                }
                #pragma unroll
                for (int r = 0; r < RPT; ++r) {
                    ull xx = pack2(xv[r][dd], xv[r][dd]);
                    #pragma unroll
                    for (int j = 0; j < 4 * G; ++j) acc[r][j] = fma2(xx, w[j], acc[r][j]);
                }
            }
        }
    }

    // ---- Phase 2: bias + tanh (separate tv registers) ----
    float tv[RPT][F];
    #pragma unroll
    for (int r = 0; r < RPT; ++r)
        #pragma unroll
        for (int g = 0; g < G; ++g)
            #pragma unroll
            for (int p = 0; p < 4; ++p) {
                float lo, hi; unpack2(acc[r][g * 4 + p], lo, hi);
                int P = g * 8 + 2 * p;
                tv[r][P]     = ftanh(lo + sb0[P]);
                tv[r][P + 1] = ftanh(hi + sb0[P + 1]);
            }

    // ---- batch stats ----
    #pragma unroll
    for (int f = 0; f < F; ++f) {
        float s = 0.f, ss = 0.f;
        #pragma unroll
        for (int r = 0; r < RPT; ++r) { float v = tv[r][f]; s += v; ss += v * v; }
        #pragma unroll
        for (int o = 16; o; o >>= 1) {
            s  += __shfl_xor_sync(0xffffffffu, s, o);
            ss += __shfl_xor_sync(0xffffffffu, ss, o);
        }
        if (lane == 0) { red[f * NW + warp] = s; red[(F + f) * NW + warp] = ss; }
    }
    __syncthreads();
    if (tid < F) {
        int f = tid;
        float s = 0.f, ss = 0.f;
        #pragma unroll
        for (int w = 0; w < NW; ++w) { s += red[f * NW + w]; ss += red[(F + f) * NW + w]; }
        float mu  = s  * (1.f / B_ROWS);
        float var = ss * (1.f / B_ROWS) - mu * mu;
        float a   = sg0[f] * rsqrtf(var + BN_EPS);
        stA[f] = a;
        stB[f] = sbe0[f] - mu * a;
    }
    __syncthreads();

    // ---- Phase 3: normalize -> swizzled tile -> coalesced STG; aux in same pass ----
    float* tile = sh_x;
    float av[RPT][FA];
    #pragma unroll 1
    for (int q = 0; q < RPT; ++q) {
        float tn[F];
        #pragma unroll
        for (int f = 0; f < F; ++f) tn[f] = fmaf(stA[f], tv[q][f], stB[f]);

        #pragma unroll
        for (int part = 0; part < F / 4; ++part) {
            float4 v = make_float4(tn[part * 4], tn[part * 4 + 1],
                                   tn[part * 4 + 2], tn[part * 4 + 3]);
            *reinterpret_cast<float4*>(&tile[swz(tid, part)]) = v;
        }
        #pragma unroll
        for (int g = 0; g < G; ++g)
            #pragma unroll
            for (int k = 0; k < 2; ++k) {
                float a = sba[g * 2 + k];
                #pragma unroll
                for (int h = 0; h < 8; ++h)
                    a = fmaf(tn[g * 8 + h], swa[(g * 8 + h) * 2 + k], a);
                av[q][g * 2 + k] = ftanh(a);
            }
        __syncthreads();

        constexpr int PT = F / 4;
        #pragma unroll
        for (int jj = 0; jj < (512 * PT) / THREADS; ++jj) {
            int j    = tid + jj * THREADS;
            int row  = j / PT;
            int part = j % PT;
            int grow = q * THREADS + row;
            *reinterpret_cast<float4*>(&out_t[(ll)grow * M * 8 + m0 * 8 + part * 4]) =
                *reinterpret_cast<const float4*>(&tile[swz(row, part)]);
        }
        __syncthreads();
    }

    // ---- Phase 4: aux stats + store ----
    #pragma unroll
    for (int f = 0; f < FA; ++f) {
        float s = 0.f, ss = 0.f;
        #pragma unroll
        for (int r = 0; r < RPT; ++r) { float v = av[r][f]; s += v; ss += v * v; }
        #pragma unroll
        for (int o = 16; o; o >>= 1) {
            s  += __shfl_xor_sync(0xffffffffu, s, o);
            ss += __shfl_xor_sync(0xffffffffu, ss, o);
        }
        if (lane == 0) { red[f * NW + warp] = s; red[(FA + f) * NW + warp] = ss; }
    }
    __syncthreads();
    if (tid < FA) {
        int f = tid;
        float s = 0.f, ss = 0.f;
        #pragma unroll
        for (int w = 0; w < NW; ++w) { s += red[f * NW + w]; ss += red[(FA + f) * NW + w]; }
        float mu  = s  * (1.f / B_ROWS);
        float var = ss * (1.f / B_ROWS) - mu * mu;
        float a   = sga[f] * rsqrtf(var + BN_EPS);
        saA[f] = a;
        saB[f] = sbea[f] - mu * a;
    }
    __syncthreads();

    #pragma unroll
    for (int r = 0; r < RPT; ++r) {
        int b = tid + r * THREADS;
        ll obase = ((ll)b * M + m0) * 2;
        float4 v;
        v.x = fmaf(saA[0], av[r][0], saB[0]);
        v.y = fmaf(saA[1], av[r][1], saB[1]);
        v.z = fmaf(saA[2], av[r][2], saB[2]);
        v.w = fmaf(saA[3], av[r][3], saB[3]);
        *reinterpret_cast<float4*>(&out_a[obase]) = v;
    }
}

// ============================ L1 kernel (R2 structure) ============================
// Block = 1 root term; x (= t0 slice) read directly from global, full batch in regs.
__global__ void __launch_bounds__(THREADS, 1)
l1_kernel(const float* __restrict__ xin,
          const float* __restrict__ Wp,  const float* __restrict__ bp,
          const float* __restrict__ gp,  const float* __restrict__ bep,
          const float* __restrict__ Wap, const float* __restrict__ bap,
          const float* __restrict__ gap, const float* __restrict__ beap,
          float* __restrict__ out_t, float* __restrict__ out_a, int M)
{
    constexpr int F = 8, FA = 2;

    __shared__ float sh_w[512];
    __shared__ float sb0[F], sg0[F], sbe0[F];
    __shared__ float swa[16];
    __shared__ float sba[FA], sga[FA], sbea[FA];
    __shared__ float red[F * NW * 2];
    __shared__ float stA[F], stB[F];
    __shared__ float saA[FA], saB[FA];

    const int tid  = threadIdx.x;
    const int lane = tid & 31;
    const int warp = tid >> 5;
    const int m0   = blockIdx.x;

    for (int i = tid; i < 512; i += THREADS) sh_w[i] = Wp[(ll)m0 * 512 + i];
    if (tid < F) {
        sb0[tid]  = bp[m0 * 8 + tid];
        sg0[tid]  = gp[m0 * 8 + tid];
        sbe0[tid] = bep[m0 * 8 + tid];
    }
    if (tid < 16) swa[tid] = Wap[m0 * 16 + tid];
    if (tid < FA) {
        sba[tid]  = bap[m0 * 2 + tid];
        sga[tid]  = gap[m0 * 2 + tid];
        sbea[tid] = beap[m0 * 2 + tid];
    }
    __syncthreads();

    const float* xptr[RPT];
    #pragma unroll
    for (int r = 0; r < RPT; ++r)
        xptr[r] = xin + (ll)(tid + r * THREADS) * 65536 + (ll)m0 * 64;

    ull acc[RPT][4];
    #pragma unroll
    for (int r = 0; r < RPT; ++r)
        #pragma unroll
        for (int j = 0; j < 4; ++j) acc[r][j] = 0ull;

    #pragma unroll 1
    for (int c = 0; c < 16; ++c) {
        float xv[RPT][4];
        #pragma unroll
        for (int r = 0; r < RPT; ++r) {
            const float4 v = *reinterpret_cast<const float4*>(xptr[r] + c * 4);
            xv[r][0] = v.x; xv[r][1] = v.y; xv[r][2] = v.z; xv[r][3] = v.w;
        }
        #pragma unroll
        for (int dd = 0; dd < 4; ++dd) {
            ull w[4];
            #pragma unroll
            for (int p = 0; p < 4; ++p)
                w[p] = *reinterpret_cast<const ull*>(&sh_w[(c * 4 + dd) * 8 + 2 * p]);
            #pragma unroll
            for (int r = 0; r < RPT; ++r) {
                ull xx = pack2(xv[r][dd], xv[r][dd]);
                #pragma unroll
                for (int j = 0; j < 4; ++j) acc[r][j] = fma2(xx, w[j], acc[r][j]);
            }
        }
    }

    float tv[RPT][F];
    #pragma unroll
    for (int r = 0; r < RPT; ++r)
        #pragma unroll
        for (int p = 0; p < 4; ++p) {
            float lo, hi; unpack2(acc[r][p], lo, hi);
            int P = 2 * p;
            tv[r][P]     = ftanh(lo + sb0[P]);
            tv[r][P + 1] = ftanh(hi + sb0[P + 1]);
        }

    #pragma unroll
    for (int f = 0; f < F; ++f) {
        float s = 0.f, ss = 0.f;
        #pragma unroll
        for (int r = 0; r < RPT; ++r) { float v = tv[r][f]; s += v; ss += v * v; }
        #pragma unroll
        for (int o = 16; o; o >>= 1) {
            s  += __shfl_xor_sync(0xffffffffu, s, o);
            ss += __shfl_xor_sync(0xffffffffu, ss, o);
        }
        if (lane == 0) { red[f * NW + warp] = s; red[(F + f) * NW + warp] = ss; }
    }
    __syncthreads();
    if (tid < F) {
        int f = tid;
        float s = 0.f, ss = 0.f;
        #pragma unroll
        for (int w = 0; w < NW; ++w) { s += red[f * NW + w]; ss += red[(F + f) * NW + w]; }
        float mu  = s  * (1.f / B_ROWS);
        float var = ss * (1.f / B_ROWS) - mu * mu;
        float a   = sg0[f] * rsqrtf(var + BN_EPS);
        stA[f] = a;
        stB[f] = sbe0[f] - mu * a;
    }
    __syncthreads();

    float av[RPT][FA];
    #pragma unroll
    for (int r = 0; r < RPT; ++r) {
        int b = tid + r * THREADS;
        float tn[F];
        #pragma unroll
        for (int f = 0; f < F; ++f) tn[f] = fmaf(stA[f], tv[r][f], stB[f]);

        ll obase = ((ll)b * M + m0) * 8;
        #pragma unroll
        for (int q = 0; q < 2; ++q) {
            float4 v = make_float4(tn[q * 4], tn[q * 4 + 1], tn[q * 4 + 2], tn[q * 4 + 3]);
            *reinterpret_cast<float4*>(&out_t[obase + q * 4]) = v;
        }
        #pragma unroll
        for (int k = 0; k < 2; ++k) {
            float a = sba[k];
            #pragma unroll
            for (int h = 0; h < 8; ++h)
                a = fmaf(tn[h], swa[h * 2 + k], a);
            av[r][k] = ftanh(a);
        }
    }

    #pragma unroll
    for (int f = 0; f < FA; ++f) {
        float s = 0.f, ss = 0.f;
        #pragma unroll
        for (int r = 0; r < RPT; ++r) { float v = av[r][f]; s += v; ss += v * v; }
        #pragma unroll
        for (int o = 16; o; o >>= 1) {
            s  += __shfl_xor_sync(0xffffffffu, s, o);
            ss += __shfl_xor_sync(0xffffffffu, ss, o);
        }
        if (lane == 0) { red[f * NW + warp] = s; red[(FA + f) * NW + warp] = ss; }
    }
    __syncthreads();
    if (tid < FA) {
        int f = tid;
        float s = 0.f, ss = 0.f;
        #pragma unroll
        for (int w = 0; w < NW; ++w) { s += red[f * NW + w]; ss += red[(FA + f) * NW + w]; }
        float mu  = s  * (1.f / B_ROWS);
        float var = ss * (1.f / B_ROWS) - mu * mu;
        float a   = sga[f] * rsqrtf(var + BN_EPS);
        saA[f] = a;
        saB[f] = sbea[f] - mu * a;
    }
    __syncthreads();

    #pragma unroll
    for (int r = 0; r < RPT; ++r) {
        int b = tid + r * THREADS;
        ll obase = ((ll)b * M + m0) * 2;
        float2 v;
        v.x = fmaf(saA[0], av[r][0], saB[0]);
        v.y = fmaf(saA[1], av[r][1], saB[1]);
        *reinterpret_cast<float2*>(&out_a[obase]) = v;
    }
}

// Output layout: (aux0, aux1, t0, t1) flattened, fp32
static const ll OFF_A0 = 0;
static const ll OFF_A1 = 2048LL * 8192 * 2;            // 33,554,432
static const ll OFF_T0 = OFF_A1 + 2048LL * 1024 * 2;   // 37,748,736
static const ll OFF_T1 = OFF_T0 + 2048LL * 8192 * 8;   // 171,966,464

extern "C" void kernel_launch(void* const* d_in, const int* in_sizes, int n_in,
                              void* d_out, int out_size)
{
    const float* x    = (const float*)d_in[0];
    const float* W0   = (const float*)d_in[1];
    const float* b0   = (const float*)d_in[2];
    const float* g0   = (const float*)d_in[3];
    const float* be0  = (const float*)d_in[4];
    const float* Wa0  = (const float*)d_in[5];
    const float* ba0  = (const float*)d_in[6];
    const float* ga0  = (const float*)d_in[7];
    const float* bea0 = (const float*)d_in[8];
    const float* W1   = (const float*)d_in[9];
    const float* b1   = (const float*)d_in[10];
    const float* g1   = (const float*)d_in[11];
    const float* be1  = (const float*)d_in[12];
    const float* Wa1  = (const float*)d_in[13];
    const float* ba1  = (const float*)d_in[14];
    const float* ga1  = (const float*)d_in[15];
    const float* bea1 = (const float*)d_in[16];

    float* out  = (float*)d_out;
    float* aux0 = out + OFF_A0;
    float* aux1 = out + OFF_A1;
    float* t0   = out + OFF_T0;
    float* t1   = out + OFF_T1;

    // L0 dynamic smem: sh_x (2048*16) + weights/params/reduction scratch
    const int s0 = (B_ROWS * 16 + 2 * 512 + 16 * NW * 2 + 2 * 16 + 2 * 4
                    + 3 * 16 + 2 * 16 + 3 * 4) * 4;
    cudaFuncSetAttribute(reinterpret_cast<const void*>(l0_kernel),
                         cudaFuncAttributeMaxDynamicSharedMemorySize, s0);

    // Layer 0: 4096 blocks split into 3 launches (block-offset) so ncu's
    // skip-5-capture-1 lands on an L0 launch (3 of every 4 launches are L0).
    l0_kernel<<<1365, THREADS, s0>>>(x, 0,    W0, b0, g0, be0, Wa0, ba0, ga0, bea0, t0, aux0, 8192);
    l0_kernel<<<1365, THREADS, s0>>>(x, 1365, W0, b0, g0, be0, Wa0, ba0, ga0, bea0, t0, aux0, 8192);
    l0_kernel<<<1366, THREADS, s0>>>(x, 2730, W0, b0, g0, be0, Wa0, ba0, ga0, bea0, t0, aux0, 8192);

    // Layer 1: 1024 roots, direct-load variant (best measured: 216.8us)
    l1_kernel<<<1024, THREADS>>>(
        t0, W1, b1, g1, be1, Wa1, ba1, ga1, bea1, t1, aux1, 1024);
}